// round 6
// baseline (speedup 1.0000x reference)
#include <cuda_runtime.h>
#include <cuda_fp16.h>
#include <cuda_bf16.h>

#define N_NODES_MAX 100000
#define HIDDEN 64
#define ZS_STRIDE 68   // padded z row stride (floats) to avoid bank conflicts

// Per-node fp16 projections WITH b1/2 pre-folded:
//   u' = z @ W1[0:64,:]  + 0.5*b1
//   v' = z @ W1[64:128,:] + 0.5*b1
__device__ uint4 g_u[N_NODES_MAX * 8];
__device__ uint4 g_v[N_NODES_MAX * 8];
__device__ int   g_idx_is64;

// packed f32x2 fma: acc.lo += a.lo*b.lo ; acc.hi += a.hi*b.hi
#define FMA_F32X2(acc, a, b) \
    asm("fma.rn.f32x2 %0, %1, %2, %0;" : "+l"(acc) : "l"(a), "l"(b))

__device__ __forceinline__ unsigned long long dup_f32x2(float v) {
    unsigned long long r;
    asm("mov.b64 %0, {%1, %1};" : "=l"(r) : "r"(__float_as_uint(v)));
    return r;
}
__device__ __forceinline__ unsigned long long pack_f32x2(float lo, float hi) {
    unsigned long long r;
    asm("mov.b64 %0, {%1, %2};" : "=l"(r)
        : "r"(__float_as_uint(lo)), "r"(__float_as_uint(hi)));
    return r;
}
__device__ __forceinline__ void unpack_f32x2(unsigned long long p,
                                             float& lo, float& hi) {
    unsigned a, b;
    asm("mov.b64 {%0, %1}, %2;" : "=r"(a), "=r"(b) : "l"(p));
    lo = __uint_as_float(a);
    hi = __uint_as_float(b);
}

// ---------------------------------------------------------------------------
// Precompute: block = 256 threads = 64 node-pairs x 4 output-groups,
// covering 128 nodes x 128 combined output cols.
// thread (pair pr, group g): nodes {2pr, 2pr+1}, output cols n0=32g..n0+31.
// Weights staged transposed in smem wt[k][n]; z rows staged in smem.
// Inner loop: per k, 8x LDS.128 (w pairs, shared by both nodes) + 32x FFMA2.
// Accumulators initialized with 0.5*b1 (bias fold).
// ---------------------------------------------------------------------------
__global__ __launch_bounds__(256)
void precompute_uv_kernel(const float* __restrict__ z,
                          const float* __restrict__ W1,
                          const float* __restrict__ b1,
                          const int* __restrict__ ei_as_i32,
                          int n_nodes) {
    extern __shared__ __align__(16) float sm[];
    float* wt  = sm;                       // [64][128]
    float* zs  = sm + 64 * 128;            // [128][ZS_STRIDE]
    float* b1c = zs + 128 * ZS_STRIDE;     // [128]: 0.5*b1 combined

    __shared__ int s_nz[4];
    const int tid  = threadIdx.x;
    const int base = blockIdx.x * 128;

    // dtype detection (block 0, warps 0-3)
    if (blockIdx.x == 0 && tid < 128) {
        int nz = (ei_as_i32[2 * tid + 1] != 0) ? 1 : 0;
        unsigned b = __ballot_sync(0xffffffffu, nz);
        if ((tid & 31) == 0) s_nz[tid >> 5] = (b != 0);
    }

    // Stage transposed weights. W1 linear idx i = j*64+m (j=0..127, m=0..63):
    //   j<64 : wt[j][m]           (u part, k=j, n=m)
    //   j>=64: wt[j-64][64+m]     (v part, k=j-64, n=64+m)
    for (int i4 = tid; i4 < 2048; i4 += 256) {
        const int i = i4 * 4;
        const int j = i >> 6, m = i & 63;
        const float4 w4 = ((const float4*)W1)[i4];
        float* dst = (j < HIDDEN) ? &wt[j * 128 + m]
                                  : &wt[(j - HIDDEN) * 128 + HIDDEN + m];
        *(float4*)dst = w4;
    }

    // Stage z rows for this block's 128 nodes (coalesced), zero-padded.
    {
        const float4* zg = (const float4*)(z + (size_t)base * HIDDEN);
        for (int i4 = tid; i4 < 2048; i4 += 256) {
            const int node = i4 >> 4;       // 16 float4 per node
            const int k4   = i4 & 15;
            float4 v = make_float4(0.f, 0.f, 0.f, 0.f);
            if (base + node < n_nodes) v = zg[node * 16 + k4];
            *(float4*)&zs[node * ZS_STRIDE + k4 * 4] = v;
        }
    }
    if (tid < 128) b1c[tid] = 0.5f * b1[(tid < HIDDEN) ? tid : tid - HIDDEN];
    __syncthreads();

    if (blockIdx.x == 0 && tid == 0)
        g_idx_is64 = !(s_nz[0] | s_nz[1] | s_nz[2] | s_nz[3]);

    const int g  = tid & 3;
    const int pr = tid >> 2;
    const int n0 = g * 32;
    const int nodeA = pr * 2, nodeB = pr * 2 + 1;

    // 16 output pairs per node, acc initialized with folded bias.
    unsigned long long accA[16], accB[16];
    #pragma unroll
    for (int q = 0; q < 16; q++) {
        const unsigned long long ini =
            pack_f32x2(b1c[n0 + 2 * q], b1c[n0 + 2 * q + 1]);
        accA[q] = ini;
        accB[q] = ini;
    }

    const float* zA = &zs[nodeA * ZS_STRIDE];
    const float* zB = &zs[nodeB * ZS_STRIDE];

    for (int k0 = 0; k0 < HIDDEN; k0 += 4) {
        const float4 a4 = *(const float4*)&zA[k0];
        const float4 b4 = *(const float4*)&zB[k0];
        unsigned long long zdA[4], zdB[4];
        zdA[0] = dup_f32x2(a4.x); zdA[1] = dup_f32x2(a4.y);
        zdA[2] = dup_f32x2(a4.z); zdA[3] = dup_f32x2(a4.w);
        zdB[0] = dup_f32x2(b4.x); zdB[1] = dup_f32x2(b4.y);
        zdB[2] = dup_f32x2(b4.z); zdB[3] = dup_f32x2(b4.w);

        #pragma unroll
        for (int kk = 0; kk < 4; kk++) {
            const ulonglong2* wrow =
                (const ulonglong2*)&wt[(k0 + kk) * 128 + n0];
            #pragma unroll
            for (int p = 0; p < 8; p++) {
                const ulonglong2 w2 = wrow[p];
                FMA_F32X2(accA[2 * p],     w2.x, zdA[kk]);
                FMA_F32X2(accA[2 * p + 1], w2.y, zdA[kk]);
                FMA_F32X2(accB[2 * p],     w2.x, zdB[kk]);
                FMA_F32X2(accB[2 * p + 1], w2.y, zdB[kk]);
            }
        }
    }

    // Epilogue: pack to half2 and store 4x uint4 per node.
    #pragma unroll
    for (int s = 0; s < 2; s++) {
        const int nl = (s == 0) ? nodeA : nodeB;
        const int gn = base + nl;
        if (gn >= n_nodes) continue;
        const unsigned long long* acc = (s == 0) ? accA : accB;

        uint4 out4[4];
        __half2* hp = (__half2*)out4;
        #pragma unroll
        for (int q = 0; q < 16; q++) {
            float lo, hi;
            unpack_f32x2(acc[q], lo, hi);
            hp[q] = __floats2half2_rn(lo, hi);
        }
        uint4* dst = (n0 < HIDDEN)
                   ? &g_u[(size_t)gn * 8 + (n0 >> 3)]
                   : &g_v[(size_t)gn * 8 + ((n0 - HIDDEN) >> 3)];
        #pragma unroll
        for (int q = 0; q < 4; q++) dst[q] = out4[q];
    }
}

// ---------------------------------------------------------------------------
// One lane's 8-column partial dot (b1 already folded into u/v).
// ---------------------------------------------------------------------------
__device__ __forceinline__ float oct_partial(uint4 u, uint4 v,
                                             const float* __restrict__ ww) {
    const __half2* up = (const __half2*)&u;
    const __half2* vp = (const __half2*)&v;
    const __half2 z2 = __float2half2_rn(0.f);
    float s = 0.f;
    #pragma unroll
    for (int i = 0; i < 4; i++) {
        const __half2 h = __hmax2(__hadd2(up[i], vp[i]), z2);
        const float2 hf = __half22float2(h);
        s = fmaf(hf.x, ww[2 * i], s);
        s = fmaf(hf.y, ww[2 * i + 1], s);
    }
    return s;
}

// ---------------------------------------------------------------------------
// Edge kernel: 32 edges/warp; coalesced index load then 8 unrolled substeps
// of 4 edges; 8 lanes/edge gather one 16B chunk of u'[row], v'[col].
// ---------------------------------------------------------------------------
__global__ __launch_bounds__(256)
void edge_decode_kernel(const void* __restrict__ ei_raw,
                        const float* __restrict__ W2,
                        const float* __restrict__ b2,
                        float* __restrict__ out,
                        int n_edges) {
    const int lane = threadIdx.x & 31;
    const int oct  = lane >> 3;
    const int j    = lane & 7;

    const long long base =
        (long long)((blockIdx.x * blockDim.x + threadIdx.x) >> 5) * 32;
    if (base >= n_edges) return;

    const int is64 = g_idx_is64;
    const long long* __restrict__ ei64 = (const long long*)ei_raw;
    const int*       __restrict__ ei32 = (const int*)ei_raw;

    const long long eL = base + lane;
    const bool haveL = eL < n_edges;
    int r_all, c_all;
    if (is64) {
        r_all = haveL ? (int)ei64[eL] : 0;
        c_all = haveL ? (int)ei64[(long long)n_edges + eL] : 0;
    } else {
        r_all = haveL ? ei32[eL] : 0;
        c_all = haveL ? ei32[(long long)n_edges + eL] : 0;
    }

    float ww[8];
    #pragma unroll
    for (int i = 0; i < 8; i++) ww[i] = W2[8 * j + i];
    const float bias2 = b2[0];

    const bool full_tile = (base + 32) <= (long long)n_edges;

    #pragma unroll
    for (int s = 0; s < 8; s++) {
        const int e_off = s * 4 + oct;
        const int r = __shfl_sync(0xffffffffu, r_all, e_off);
        const int c = __shfl_sync(0xffffffffu, c_all, e_off);

        const uint4 u = g_u[(size_t)r * 8 + j];
        const uint4 v = g_v[(size_t)c * 8 + j];

        float acc = oct_partial(u, v, ww);
        acc += __shfl_xor_sync(0xffffffffu, acc, 1);
        acc += __shfl_xor_sync(0xffffffffu, acc, 2);
        acc += __shfl_xor_sync(0xffffffffu, acc, 4);

        if (j == 0) {
            const long long e = base + e_off;
            if (full_tile || e < n_edges) out[e] = acc + bias2;
        }
    }
}

// ---------------------------------------------------------------------------
// Launch. Inputs: z, edge_index [2,E], W1, b1, W2, b2. Output: f32 [E,1].
// ---------------------------------------------------------------------------
extern "C" void kernel_launch(void* const* d_in, const int* in_sizes, int n_in,
                              void* d_out, int out_size) {
    const float* z  = (const float*)d_in[0];
    const void*  ei = d_in[1];
    const float* W1 = (const float*)d_in[2];
    const float* b1 = (const float*)d_in[3];
    const float* W2 = (const float*)d_in[4];
    const float* b2 = (const float*)d_in[5];
    float* out = (float*)d_out;

    const int n_nodes = in_sizes[0] / HIDDEN;
    const int n_edges = in_sizes[1] / 2;

    // Phase 1: per-node fp16 projections (FFMA2, bias folded).
    {
        const int smem_bytes = (64 * 128 + 128 * ZS_STRIDE + 128) * 4;
        cudaFuncSetAttribute(precompute_uv_kernel,
                             cudaFuncAttributeMaxDynamicSharedMemorySize,
                             smem_bytes);
        const int blocks = (n_nodes + 127) / 128;
        precompute_uv_kernel<<<blocks, 256, smem_bytes>>>(
            z, W1, b1, (const int*)ei, n_nodes);
    }

    // Phase 2: edge decode.
    {
        const int threads = 256;
        const int edges_per_block = 256;   // 8 warps x 32 edges
        const int blocks = (n_edges + edges_per_block - 1) / edges_per_block;
        edge_decode_kernel<<<blocks, threads>>>(ei, W2, b2, out, n_edges);
    }
}

// round 7
// speedup vs baseline: 3.1811x; 3.1811x over previous
#include <cuda_runtime.h>
#include <cuda_fp16.h>
#include <cuda_bf16.h>

#define N_NODES_MAX 100000
#define HIDDEN 64
#define STRIDE_H 72   // smem stride (halves): 36 words ≡ 4 (mod 32) -> conflict-free B frags

// Per-node fp16 projections WITH b1/2 pre-folded:
//   u' = z @ W1[0:64,:]   + 0.5*b1
//   v' = z @ W1[64:128,:] + 0.5*b1
__device__ uint4 g_u[N_NODES_MAX * 8];
__device__ uint4 g_v[N_NODES_MAX * 8];
__device__ int   g_idx_is64;

#define MMA16816(c0, c1, c2, c3, a0, a1, a2, a3, b0, b1)                  \
    asm volatile(                                                          \
        "mma.sync.aligned.m16n8k16.row.col.f32.f16.f16.f32 "              \
        "{%0,%1,%2,%3}, {%4,%5,%6,%7}, {%8,%9}, {%0,%1,%2,%3};"           \
        : "+f"(c0), "+f"(c1), "+f"(c2), "+f"(c3)                           \
        : "r"(a0), "r"(a1), "r"(a2), "r"(a3), "r"(b0), "r"(b1))

__device__ __forceinline__ unsigned h2_as_u32(__half2 h) {
    return *(unsigned*)&h;
}

// ---------------------------------------------------------------------------
// Precompute via tensor cores. Block = 256 threads (8 warps) = 128 nodes.
// Warp w handles 16 nodes. GEMM: C[16 nodes][128 outs] = Z[16,64] @ Wc[64,128]
// as 16 n-tiles (m16n8k16) x 4 k-tiles, with split-precision fp16 operands:
//   acc = zh@wh + zh@wl + zl@wh  (fp32 accum; dropped zl@wl ~ 2^-22)
// Weights (hi/lo) staged transposed in smem [n][k]; bias 0.5*b1 folded into
// the accumulator init. Block 0 also detects the edge_index dtype.
// ---------------------------------------------------------------------------
__global__ __launch_bounds__(256)
void precompute_uv_kernel(const float* __restrict__ z,
                          const float* __restrict__ W1,
                          const float* __restrict__ b1,
                          const int* __restrict__ ei_as_i32,
                          int n_nodes) {
    __shared__ __half whh[128 * STRIDE_H];
    __shared__ __half whl[128 * STRIDE_H];
    __shared__ float  b1c[128];
    __shared__ int    s_nz[4];

    const int tid = threadIdx.x;

    // dtype detection (block 0, warps 0-3 fully active)
    if (blockIdx.x == 0 && tid < 128) {
        int nz = (ei_as_i32[2 * tid + 1] != 0) ? 1 : 0;
        unsigned b = __ballot_sync(0xffffffffu, nz);
        if ((tid & 31) == 0) s_nz[tid >> 5] = (b != 0);
    }

    // Stage split-precision transposed weights.
    // W1 linear i = j*64+m (j = 0..127 row, m = 0..63 col):
    //   j<64 : output n=m,    k=j      (u part)
    //   j>=64: output n=64+m, k=j-64   (v part)
    for (int i = tid; i < 128 * HIDDEN; i += 256) {
        const int j = i >> 6, m = i & 63;
        const int n = (j < HIDDEN) ? m : (HIDDEN + m);
        const int k = (j < HIDDEN) ? j : (j - HIDDEN);
        const float w = W1[i];
        const __half hi = __float2half_rn(w);
        const __half lo = __float2half_rn(w - __half2float(hi));
        whh[n * STRIDE_H + k] = hi;
        whl[n * STRIDE_H + k] = lo;
    }
    if (tid < 128) b1c[tid] = 0.5f * b1[tid & (HIDDEN - 1)];
    __syncthreads();

    if (blockIdx.x == 0 && tid == 0)
        g_idx_is64 = !(s_nz[0] | s_nz[1] | s_nz[2] | s_nz[3]);

    const int warp = tid >> 5, lane = tid & 31;
    const int g = lane >> 2, tig = lane & 3;
    const long long wbase = (long long)blockIdx.x * 128 + warp * 16;
    if (wbase >= n_nodes) return;

    // Accumulators: 16 n-tiles x 4 f32, init with folded bias.
    float acc[16][4];
    #pragma unroll
    for (int t = 0; t < 16; t++) {
        const int c = t * 8 + tig * 2;
        acc[t][0] = b1c[c];     acc[t][1] = b1c[c + 1];
        acc[t][2] = b1c[c];     acc[t][3] = b1c[c + 1];
    }

    // Rows this thread touches (clamped; stores predicated later).
    const long long r0 = (wbase + g     < n_nodes) ? (wbase + g)     : (n_nodes - 1);
    const long long r1 = (wbase + g + 8 < n_nodes) ? (wbase + g + 8) : (n_nodes - 1);

    #pragma unroll
    for (int kt = 0; kt < 4; kt++) {
        const int k0 = kt * 16;
        // A fragments: a0 (r0, k0+tig*2), a1 (r1, same), a2 (r0, +8), a3 (r1, +8)
        const float2 f0 = *(const float2*)&z[r0 * HIDDEN + k0 + tig * 2];
        const float2 f1 = *(const float2*)&z[r1 * HIDDEN + k0 + tig * 2];
        const float2 f2 = *(const float2*)&z[r0 * HIDDEN + k0 + 8 + tig * 2];
        const float2 f3 = *(const float2*)&z[r1 * HIDDEN + k0 + 8 + tig * 2];

        __half2 h; float2 hf;
        unsigned ah[4], al[4];
        h = __floats2half2_rn(f0.x, f0.y); ah[0] = h2_as_u32(h);
        hf = __half22float2(h);
        al[0] = h2_as_u32(__floats2half2_rn(f0.x - hf.x, f0.y - hf.y));
        h = __floats2half2_rn(f1.x, f1.y); ah[1] = h2_as_u32(h);
        hf = __half22float2(h);
        al[1] = h2_as_u32(__floats2half2_rn(f1.x - hf.x, f1.y - hf.y));
        h = __floats2half2_rn(f2.x, f2.y); ah[2] = h2_as_u32(h);
        hf = __half22float2(h);
        al[2] = h2_as_u32(__floats2half2_rn(f2.x - hf.x, f2.y - hf.y));
        h = __floats2half2_rn(f3.x, f3.y); ah[3] = h2_as_u32(h);
        hf = __half22float2(h);
        al[3] = h2_as_u32(__floats2half2_rn(f3.x - hf.x, f3.y - hf.y));

        #pragma unroll
        for (int t = 0; t < 16; t++) {
            const int nb = t * 8 + g;
            const unsigned bh0 = *(const unsigned*)&whh[nb * STRIDE_H + k0 + tig * 2];
            const unsigned bh1 = *(const unsigned*)&whh[nb * STRIDE_H + k0 + 8 + tig * 2];
            const unsigned bl0 = *(const unsigned*)&whl[nb * STRIDE_H + k0 + tig * 2];
            const unsigned bl1 = *(const unsigned*)&whl[nb * STRIDE_H + k0 + 8 + tig * 2];
            MMA16816(acc[t][0], acc[t][1], acc[t][2], acc[t][3],
                     ah[0], ah[1], ah[2], ah[3], bh0, bh1);
            MMA16816(acc[t][0], acc[t][1], acc[t][2], acc[t][3],
                     ah[0], ah[1], ah[2], ah[3], bl0, bl1);
            MMA16816(acc[t][0], acc[t][1], acc[t][2], acc[t][3],
                     al[0], al[1], al[2], al[3], bh0, bh1);
        }
    }

    // Epilogue: D fragment (row g: c0,c1 / row g+8: c2,c3), cols t*8+tig*2.
    const bool ok0 = (wbase + g)     < n_nodes;
    const bool ok1 = (wbase + g + 8) < n_nodes;
    __half2* U = (__half2*)g_u;
    __half2* V = (__half2*)g_v;
    #pragma unroll
    for (int t = 0; t < 16; t++) {
        const __half2 d0 = __floats2half2_rn(acc[t][0], acc[t][1]);
        const __half2 d1 = __floats2half2_rn(acc[t][2], acc[t][3]);
        if (t < 8) {
            const int ci = t * 4 + tig;              // half2 col in u
            if (ok0) U[r0 * 32 + ci] = d0;
            if (ok1) U[r1 * 32 + ci] = d1;
        } else {
            const int ci = (t - 8) * 4 + tig;        // half2 col in v
            if (ok0) V[r0 * 32 + ci] = d0;
            if (ok1) V[r1 * 32 + ci] = d1;
        }
    }
}

// ---------------------------------------------------------------------------
// One lane's 8-column partial dot (b1 already folded into u/v).
// ---------------------------------------------------------------------------
__device__ __forceinline__ float oct_partial(uint4 u, uint4 v,
                                             const float* __restrict__ ww) {
    const __half2* up = (const __half2*)&u;
    const __half2* vp = (const __half2*)&v;
    const __half2 z2 = __float2half2_rn(0.f);
    float s = 0.f;
    #pragma unroll
    for (int i = 0; i < 4; i++) {
        const __half2 h = __hmax2(__hadd2(up[i], vp[i]), z2);
        const float2 hf = __half22float2(h);
        s = fmaf(hf.x, ww[2 * i], s);
        s = fmaf(hf.y, ww[2 * i + 1], s);
    }
    return s;
}

// ---------------------------------------------------------------------------
// Edge kernel: 32 edges/warp; coalesced index load then 8 unrolled substeps
// of 4 edges; 8 lanes/edge gather one 16B chunk of u'[row], v'[col].
// ---------------------------------------------------------------------------
__global__ __launch_bounds__(256)
void edge_decode_kernel(const void* __restrict__ ei_raw,
                        const float* __restrict__ W2,
                        const float* __restrict__ b2,
                        float* __restrict__ out,
                        int n_edges) {
    const int lane = threadIdx.x & 31;
    const int oct  = lane >> 3;
    const int j    = lane & 7;

    const long long base =
        (long long)((blockIdx.x * blockDim.x + threadIdx.x) >> 5) * 32;
    if (base >= n_edges) return;

    const int is64 = g_idx_is64;
    const long long* __restrict__ ei64 = (const long long*)ei_raw;
    const int*       __restrict__ ei32 = (const int*)ei_raw;

    const long long eL = base + lane;
    const bool haveL = eL < n_edges;
    int r_all, c_all;
    if (is64) {
        r_all = haveL ? (int)ei64[eL] : 0;
        c_all = haveL ? (int)ei64[(long long)n_edges + eL] : 0;
    } else {
        r_all = haveL ? ei32[eL] : 0;
        c_all = haveL ? ei32[(long long)n_edges + eL] : 0;
    }

    float ww[8];
    #pragma unroll
    for (int i = 0; i < 8; i++) ww[i] = W2[8 * j + i];
    const float bias2 = b2[0];

    const bool full_tile = (base + 32) <= (long long)n_edges;

    #pragma unroll
    for (int s = 0; s < 8; s++) {
        const int e_off = s * 4 + oct;
        const int r = __shfl_sync(0xffffffffu, r_all, e_off);
        const int c = __shfl_sync(0xffffffffu, c_all, e_off);

        const uint4 u = g_u[(size_t)r * 8 + j];
        const uint4 v = g_v[(size_t)c * 8 + j];

        float acc = oct_partial(u, v, ww);
        acc += __shfl_xor_sync(0xffffffffu, acc, 1);
        acc += __shfl_xor_sync(0xffffffffu, acc, 2);
        acc += __shfl_xor_sync(0xffffffffu, acc, 4);

        if (j == 0) {
            const long long e = base + e_off;
            if (full_tile || e < n_edges) out[e] = acc + bias2;
        }
    }
}

// ---------------------------------------------------------------------------
// Launch. Inputs: z, edge_index [2,E], W1, b1, W2, b2. Output: f32 [E,1].
// ---------------------------------------------------------------------------
extern "C" void kernel_launch(void* const* d_in, const int* in_sizes, int n_in,
                              void* d_out, int out_size) {
    const float* z  = (const float*)d_in[0];
    const void*  ei = d_in[1];
    const float* W1 = (const float*)d_in[2];
    const float* b1 = (const float*)d_in[3];
    const float* W2 = (const float*)d_in[4];
    const float* b2 = (const float*)d_in[5];
    float* out = (float*)d_out;

    const int n_nodes = in_sizes[0] / HIDDEN;
    const int n_edges = in_sizes[1] / 2;

    // Phase 1: tensor-core per-node projections (split-precision fp16 mma).
    {
        const int blocks = (n_nodes + 127) / 128;
        precompute_uv_kernel<<<blocks, 256>>>(z, W1, b1, (const int*)ei, n_nodes);
    }

    // Phase 2: edge decode.
    {
        const int threads = 256;
        const int edges_per_block = 256;   // 8 warps x 32 edges
        const int blocks = (n_edges + edges_per_block - 1) / edges_per_block;
        edge_decode_kernel<<<blocks, threads>>>(ei, W2, b2, out, n_edges);
    }
}

// round 9
// speedup vs baseline: 3.2501x; 1.0217x over previous
#include <cuda_runtime.h>
#include <cuda_fp16.h>
#include <cuda_bf16.h>

#define N_NODES_MAX 100000
#define HIDDEN 64
#define STRIDE_H 72    // weight smem stride (halves)
#define CST_STRIDE 68  // C-stage stride (half2 units) -> conflict-free STS

// Per-node fp16 projections with |W2| and 0.5*b1 folded in:
//   u''_k = (z @ W1[0:64,:])_k  * |w2_k| + 0.5*b1_k*|w2_k|
//   v''_k = (z @ W1[64:128,:])_k* |w2_k| + 0.5*b1_k*|w2_k|
// Edge: out = sum_k sign(w2_k) * relu(u''_k + v''_k) + b2
__device__ uint4 g_u[N_NODES_MAX * 8];
__device__ uint4 g_v[N_NODES_MAX * 8];
__device__ int   g_idx_is64;

#define MMA16816(c0, c1, c2, c3, a0, a1, a2, a3, b0, b1)                  \
    asm volatile(                                                          \
        "mma.sync.aligned.m16n8k16.row.col.f32.f16.f16.f32 "              \
        "{%0,%1,%2,%3}, {%4,%5,%6,%7}, {%8,%9}, {%0,%1,%2,%3};"           \
        : "+f"(c0), "+f"(c1), "+f"(c2), "+f"(c3)                           \
        : "r"(a0), "r"(a1), "r"(a2), "r"(a3), "r"(b0), "r"(b1))

__device__ __forceinline__ unsigned h2_as_u32(__half2 h) {
    return *(unsigned*)&h;
}

// ---------------------------------------------------------------------------
// Precompute via tensor cores (split-precision fp16 mma, fp32 accum):
//   acc = zh@wh + zh@wl + zl@wh   (dropped zl@wl ~ 2^-22 relative)
// Block = 256 threads (8 warps) = 128 nodes; warp = 16 nodes.
// Weights pre-scaled by |w2| and transposed into smem [n][k] (hi/lo).
// Epilogue stages C in smem then stores fully coalesced 512B runs.
// ---------------------------------------------------------------------------
__global__ __launch_bounds__(256)
void precompute_uv_kernel(const float* __restrict__ z,
                          const float* __restrict__ W1,
                          const float* __restrict__ b1,
                          const float* __restrict__ W2,
                          const int* __restrict__ ei_as_i32,
                          int n_nodes) {
    extern __shared__ __align__(16) char smem_raw[];
    __half*  whh = (__half*)smem_raw;                    // [128][STRIDE_H]
    __half*  whl = whh + 128 * STRIDE_H;                 // [128][STRIDE_H]
    float*   b1c = (float*)(whl + 128 * STRIDE_H);       // [128]
    __half2* cst = (__half2*)(b1c + 128);                // 8 warps x 16 x CST_STRIDE

    __shared__ int s_nz[4];
    const int tid = threadIdx.x;

    // dtype detection (block 0, warps 0-3 fully active)
    if (blockIdx.x == 0 && tid < 128) {
        int nz = (ei_as_i32[2 * tid + 1] != 0) ? 1 : 0;
        unsigned b = __ballot_sync(0xffffffffu, nz);
        if ((tid & 31) == 0) s_nz[tid >> 5] = (b != 0);
    }

    // Stage split-precision, |w2|-scaled, transposed weights.
    // W1 linear i = j*64+m: j<64 -> (n=m, k=j) u-part; j>=64 -> (n=64+m, k=j-64).
    for (int i = tid; i < 128 * HIDDEN; i += 256) {
        const int j = i >> 6, m = i & 63;
        const int n = (j < HIDDEN) ? m : (HIDDEN + m);
        const int k = (j < HIDDEN) ? j : (j - HIDDEN);
        const float w = W1[i] * fabsf(W2[m]);
        const __half hi = __float2half_rn(w);
        const __half lo = __float2half_rn(w - __half2float(hi));
        whh[n * STRIDE_H + k] = hi;
        whl[n * STRIDE_H + k] = lo;
    }
    if (tid < 128) {
        const int m = tid & (HIDDEN - 1);
        b1c[tid] = 0.5f * b1[m] * fabsf(W2[m]);
    }
    __syncthreads();

    if (blockIdx.x == 0 && tid == 0)
        g_idx_is64 = !(s_nz[0] | s_nz[1] | s_nz[2] | s_nz[3]);

    const int warp = tid >> 5, lane = tid & 31;
    const int g = lane >> 2, tig = lane & 3;
    const long long wbase = (long long)blockIdx.x * 128 + warp * 16;
    if (wbase >= n_nodes) return;

    float acc[16][4];
    #pragma unroll
    for (int t = 0; t < 16; t++) {
        const int c = t * 8 + tig * 2;
        acc[t][0] = b1c[c];  acc[t][1] = b1c[c + 1];
        acc[t][2] = b1c[c];  acc[t][3] = b1c[c + 1];
    }

    const long long r0 = (wbase + g     < n_nodes) ? (wbase + g)     : (n_nodes - 1);
    const long long r1 = (wbase + g + 8 < n_nodes) ? (wbase + g + 8) : (n_nodes - 1);

    #pragma unroll
    for (int kt = 0; kt < 4; kt++) {
        const int k0 = kt * 16;
        const float2 f0 = *(const float2*)&z[r0 * HIDDEN + k0 + tig * 2];
        const float2 f1 = *(const float2*)&z[r1 * HIDDEN + k0 + tig * 2];
        const float2 f2 = *(const float2*)&z[r0 * HIDDEN + k0 + 8 + tig * 2];
        const float2 f3 = *(const float2*)&z[r1 * HIDDEN + k0 + 8 + tig * 2];

        __half2 h; float2 hf;
        unsigned ah[4], al[4];
        h = __floats2half2_rn(f0.x, f0.y); ah[0] = h2_as_u32(h);
        hf = __half22float2(h);
        al[0] = h2_as_u32(__floats2half2_rn(f0.x - hf.x, f0.y - hf.y));
        h = __floats2half2_rn(f1.x, f1.y); ah[1] = h2_as_u32(h);
        hf = __half22float2(h);
        al[1] = h2_as_u32(__floats2half2_rn(f1.x - hf.x, f1.y - hf.y));
        h = __floats2half2_rn(f2.x, f2.y); ah[2] = h2_as_u32(h);
        hf = __half22float2(h);
        al[2] = h2_as_u32(__floats2half2_rn(f2.x - hf.x, f2.y - hf.y));
        h = __floats2half2_rn(f3.x, f3.y); ah[3] = h2_as_u32(h);
        hf = __half22float2(h);
        al[3] = h2_as_u32(__floats2half2_rn(f3.x - hf.x, f3.y - hf.y));

        #pragma unroll
        for (int t = 0; t < 16; t++) {
            const int nb = t * 8 + g;
            const unsigned bh0 = *(const unsigned*)&whh[nb * STRIDE_H + k0 + tig * 2];
            const unsigned bh1 = *(const unsigned*)&whh[nb * STRIDE_H + k0 + 8 + tig * 2];
            const unsigned bl0 = *(const unsigned*)&whl[nb * STRIDE_H + k0 + tig * 2];
            const unsigned bl1 = *(const unsigned*)&whl[nb * STRIDE_H + k0 + 8 + tig * 2];
            MMA16816(acc[t][0], acc[t][1], acc[t][2], acc[t][3],
                     ah[0], ah[1], ah[2], ah[3], bh0, bh1);
            MMA16816(acc[t][0], acc[t][1], acc[t][2], acc[t][3],
                     ah[0], ah[1], ah[2], ah[3], bl0, bl1);
            MMA16816(acc[t][0], acc[t][1], acc[t][2], acc[t][3],
                     al[0], al[1], al[2], al[3], bh0, bh1);
        }
    }

    // Epilogue: stage C in smem (conflict-free), then coalesced 512B stores.
    __half2* cw = cst + warp * 16 * CST_STRIDE;
    #pragma unroll
    for (int t = 0; t < 16; t++) {
        cw[g * CST_STRIDE + t * 4 + tig]       = __floats2half2_rn(acc[t][0], acc[t][1]);
        cw[(g + 8) * CST_STRIDE + t * 4 + tig] = __floats2half2_rn(acc[t][2], acc[t][3]);
    }
    __syncwarp();

    #pragma unroll
    for (int q = 0; q < 4; q++) {
        const int nl = q * 4 + (lane >> 3);     // local node 0..15
        const int ch = lane & 7;                // uint4 chunk 0..7
        const long long gn = wbase + nl;
        if (gn < n_nodes) {
            g_u[gn * 8 + ch] = *(const uint4*)&cw[nl * CST_STRIDE + ch * 4];
            g_v[gn * 8 + ch] = *(const uint4*)&cw[nl * CST_STRIDE + 32 + ch * 4];
        }
    }
}

// ---------------------------------------------------------------------------
// One lane's 8-column signed-relu partial: b1 and |W2| folded into u/v,
// sign(+/-1) applied via exact half2 fma.
// ---------------------------------------------------------------------------
__device__ __forceinline__ float oct_partial(uint4 u, uint4 v,
                                             const __half2* __restrict__ sg) {
    const __half2* up = (const __half2*)&u;
    const __half2* vp = (const __half2*)&v;
    const __half2 z2 = __float2half2_rn(0.f);
    __half2 acc2 = __hmul2(__hmax2(__hadd2(up[0], vp[0]), z2), sg[0]);
    acc2 = __hfma2(__hmax2(__hadd2(up[1], vp[1]), z2), sg[1], acc2);
    acc2 = __hfma2(__hmax2(__hadd2(up[2], vp[2]), z2), sg[2], acc2);
    acc2 = __hfma2(__hmax2(__hadd2(up[3], vp[3]), z2), sg[3], acc2);
    const float2 f = __half22float2(acc2);
    return f.x + f.y;
}

// ---------------------------------------------------------------------------
// Edge kernel: 32 edges/warp; coalesced index load; 8 unrolled substeps of
// 4 edges; 8 lanes/edge gather one 16B chunk of u''[row], v''[col] each.
// FULL template strips all per-edge bound checks on interior tiles.
// ---------------------------------------------------------------------------
template <bool FULL>
__device__ __forceinline__
void edge_tile(const long long base, int r_all, int c_all,
               const __half2* sg, float bias2, float* __restrict__ out,
               int n_edges, int oct, int j) {
    #pragma unroll
    for (int s = 0; s < 8; s++) {
        const int e_off = s * 4 + oct;
        const int r = __shfl_sync(0xffffffffu, r_all, e_off);
        const int c = __shfl_sync(0xffffffffu, c_all, e_off);

        const uint4 u = g_u[(size_t)r * 8 + j];
        const uint4 v = g_v[(size_t)c * 8 + j];

        float acc = oct_partial(u, v, sg);
        acc += __shfl_xor_sync(0xffffffffu, acc, 1);
        acc += __shfl_xor_sync(0xffffffffu, acc, 2);
        acc += __shfl_xor_sync(0xffffffffu, acc, 4);

        if (j == 0) {
            const long long e = base + e_off;
            if (FULL || e < n_edges) out[e] = acc + bias2;
        }
    }
}

__global__ __launch_bounds__(256)
void edge_decode_kernel(const void* __restrict__ ei_raw,
                        const float* __restrict__ W2,
                        const float* __restrict__ b2,
                        float* __restrict__ out,
                        int n_edges) {
    const int lane = threadIdx.x & 31;
    const int oct  = lane >> 3;
    const int j    = lane & 7;

    const long long base =
        (long long)((blockIdx.x * blockDim.x + threadIdx.x) >> 5) * 32;
    if (base >= n_edges) return;

    const int is64 = g_idx_is64;
    const long long* __restrict__ ei64 = (const long long*)ei_raw;
    const int*       __restrict__ ei32 = (const int*)ei_raw;

    const long long eL = base + lane;
    const bool haveL = eL < n_edges;
    int r_all, c_all;
    if (is64) {
        r_all = haveL ? (int)ei64[eL] : 0;
        c_all = haveL ? (int)ei64[(long long)n_edges + eL] : 0;
    } else {
        r_all = haveL ? ei32[eL] : 0;
        c_all = haveL ? ei32[(long long)n_edges + eL] : 0;
    }

    __half2 sg[4];
    #pragma unroll
    for (int i = 0; i < 4; i++)
        sg[i] = __floats2half2_rn(copysignf(1.f, W2[8 * j + 2 * i]),
                                  copysignf(1.f, W2[8 * j + 2 * i + 1]));
    const float bias2 = b2[0];

    if (base + 32 <= (long long)n_edges)
        edge_tile<true >(base, r_all, c_all, sg, bias2, out, n_edges, oct, j);
    else
        edge_tile<false>(base, r_all, c_all, sg, bias2, out, n_edges, oct, j);
}

// ---------------------------------------------------------------------------
// Launch. Inputs: z, edge_index [2,E], W1, b1, W2, b2. Output: f32 [E,1].
// ---------------------------------------------------------------------------
extern "C" void kernel_launch(void* const* d_in, const int* in_sizes, int n_in,
                              void* d_out, int out_size) {
    const float* z  = (const float*)d_in[0];
    const void*  ei = d_in[1];
    const float* W1 = (const float*)d_in[2];
    const float* b1 = (const float*)d_in[3];
    const float* W2 = (const float*)d_in[4];
    const float* b2 = (const float*)d_in[5];
    float* out = (float*)d_out;

    const int n_nodes = in_sizes[0] / HIDDEN;
    const int n_edges = in_sizes[1] / 2;

    // Phase 1: tensor-core projections (|W2| + bias folded, coalesced stores).
    {
        const int smem_bytes = 2 * 128 * STRIDE_H * 2      // whh + whl
                             + 128 * 4                     // b1c
                             + 8 * 16 * CST_STRIDE * 4;    // C stage
        cudaFuncSetAttribute(precompute_uv_kernel,
                             cudaFuncAttributeMaxDynamicSharedMemorySize,
                             smem_bytes);
        const int blocks = (n_nodes + 127) / 128;
        precompute_uv_kernel<<<blocks, 256, smem_bytes>>>(
            z, W1, b1, W2, (const int*)ei, n_nodes);
    }

    // Phase 2: edge decode (sign-only W2, no conversions in inner loop).
    {
        const int threads = 256;
        const int edges_per_block = 256;   // 8 warps x 32 edges
        const int blocks = (n_edges + edges_per_block - 1) / edges_per_block;
        edge_decode_kernel<<<blocks, threads>>>(ei, W2, b2, out, n_edges);
    }
}